// round 2
// baseline (speedup 1.0000x reference)
#include <cuda_runtime.h>
#include <math.h>

#define B_    2
#define H_    16
#define BH    32
#define T_    2048
#define S_    2048
#define D_    64
#define U_SEL 614        // max(int(min(0.4*ln(2048),1024)), int(0.3*2048)) = max(3,614)
#define SEL_STRIDE 640
#define SCALE 0.125f     // 1/sqrt(64)
#define LOGS  7.624618986159398  // log(2048)

__device__ float g_kl[BH * T_];
__device__ int   g_sel[BH * SEL_STRIDE];

// ---------------------------------------------------------------------------
// Phase 1: KL score per query (online softmax stats, one pass over S)
// Block: 256 thr (16x16), tile 64 queries x 128 keys, register tile 4x8.
// K stored in smem with XOR(31) swizzle -> conflict-free scalar LDS.
// Cross-tile Z/A accumulated in double for ranking stability.
// ---------------------------------------------------------------------------
__global__ __launch_bounds__(256, 2)
void kl_kernel(const float* __restrict__ q, const float* __restrict__ k)
{
    __shared__ float Qs[64 * 64];    // [row][d], stride 64
    __shared__ float Ks[128 * 64];   // [col][d ^ (col&31)]

    const int tid = threadIdx.x;
    const int tx = tid & 15, ty = tid >> 4;
    const int bh = blockIdx.y;
    const int q0 = blockIdx.x * 64;

    const float* qp = q + ((size_t)bh * T_ + q0) * D_;
    const float* kp = k + (size_t)bh * S_ * D_;

    for (int lin = tid; lin < 64 * 64; lin += 256)
        Qs[lin] = qp[lin];

    float  row_m[4];
    double row_Z[4], row_A[4];
#pragma unroll
    for (int i = 0; i < 4; i++) { row_m[i] = -1e30f; row_Z[i] = 0.0; row_A[i] = 0.0; }

    for (int kt = 0; kt < S_ / 128; kt++) {
        __syncthreads();
        const float* ktp = kp + (size_t)kt * 128 * D_;
        for (int lin = tid; lin < 128 * 64; lin += 256) {
            int r = lin >> 6, d = lin & 63;
            Ks[(r << 6) + (d ^ (r & 31))] = ktp[lin];
        }
        __syncthreads();

        float acc[4][8];
#pragma unroll
        for (int i = 0; i < 4; i++)
#pragma unroll
            for (int j = 0; j < 8; j++) acc[i][j] = 0.f;

#pragma unroll 8
        for (int d = 0; d < 64; d++) {
            float qv[4], kv[8];
#pragma unroll
            for (int i = 0; i < 4; i++) qv[i] = Qs[((4 * ty + i) << 6) + d];
#pragma unroll
            for (int j = 0; j < 8; j++) {
                int c = tx + 16 * j;
                kv[j] = Ks[(c << 6) + (d ^ (c & 31))];
            }
#pragma unroll
            for (int i = 0; i < 4; i++)
#pragma unroll
                for (int j = 0; j < 8; j++)
                    acc[i][j] = fmaf(qv[i], kv[j], acc[i][j]);
        }

#pragma unroll
        for (int i = 0; i < 4; i++) {
            float tmax = -1e30f;
#pragma unroll
            for (int j = 0; j < 8; j++) {
                float s = fminf(fmaxf(acc[i][j] * SCALE, -50.f), 50.f);
                acc[i][j] = s;
                tmax = fmaxf(tmax, s);
            }
#pragma unroll
            for (int o = 8; o >= 1; o >>= 1)
                tmax = fmaxf(tmax, __shfl_xor_sync(0xffffffffu, tmax, o));

            float newm = fmaxf(row_m[i], tmax);
            float zt = 0.f, at = 0.f;
#pragma unroll
            for (int j = 0; j < 8; j++) {
                float p = acc[i][j] - newm;
                float e = __expf(p);
                zt += e;
                at = fmaf(e, p, at);
            }
#pragma unroll
            for (int o = 8; o >= 1; o >>= 1) {
                zt += __shfl_xor_sync(0xffffffffu, zt, o);
                at += __shfl_xor_sync(0xffffffffu, at, o);
            }
            float dm = row_m[i] - newm;      // <= 0, finite
            float f  = __expf(dm);           // 0 on first tile
            row_A[i] = (double)f * (row_A[i] + (double)dm * row_Z[i]) + (double)at;
            row_Z[i] = (double)f * row_Z[i] + (double)zt;
            row_m[i] = newm;
        }
    }

    if (tx == 0) {
#pragma unroll
        for (int i = 0; i < 4; i++) {
            double kl = row_A[i] / row_Z[i] - log(row_Z[i]) + LOGS;
            g_kl[bh * T_ + q0 + 4 * ty + i] = (float)kl;
        }
    }
}

// ---------------------------------------------------------------------------
// Phase 2: exact top-u selection per (b,h) via 8-bit MSB radix select,
// stable tie-break toward lower index (matches jax.lax.top_k).
// ---------------------------------------------------------------------------
__global__ void topk_kernel(int u)
{
    const int bh = blockIdx.x;
    const int tid = threadIdx.x;   // 256
    __shared__ unsigned keys[T_];
    __shared__ int hist[256];
    __shared__ int sums[256];
    __shared__ int sh_digit, sh_need;

    for (int t = tid; t < T_; t += 256) {
        unsigned b = __float_as_uint(g_kl[bh * T_ + t]);
        keys[t] = (b & 0x80000000u) ? ~b : (b | 0x80000000u);
    }
    __syncthreads();

    unsigned prefix = 0u, pmask = 0u;
    int need = u;
    for (int shift = 24; shift >= 0; shift -= 8) {
        hist[tid] = 0;
        __syncthreads();
        for (int t = tid; t < T_; t += 256) {
            unsigned kk = keys[t];
            if ((kk & pmask) == prefix)
                atomicAdd(&hist[(kk >> shift) & 255u], 1);
        }
        __syncthreads();
        if (tid == 0) {
            int cum = 0, d = 255;
            for (; d > 0; d--) {
                if (cum + hist[d] >= need) break;
                cum += hist[d];
            }
            sh_digit = d;
            sh_need  = need - cum;
        }
        __syncthreads();
        prefix |= ((unsigned)sh_digit) << shift;
        pmask  |= (255u << shift);
        need = sh_need;
        __syncthreads();
    }
    const unsigned thr = prefix;
    const int tie_take = need;

    const int base = tid * (T_ / 256);   // 8 consecutive elements / thread
    bool gtf[8], eqf[8];
    int cnt_eq = 0;
#pragma unroll
    for (int i = 0; i < 8; i++) {
        unsigned kk = keys[base + i];
        gtf[i] = (kk > thr);
        eqf[i] = (kk == thr);
        cnt_eq += eqf[i] ? 1 : 0;
    }
    // exclusive scan of eq counts (index order)
    sums[tid] = cnt_eq; __syncthreads();
    for (int off = 1; off < 256; off <<= 1) {
        int x = (tid >= off) ? sums[tid - off] : 0;
        __syncthreads();
        sums[tid] += x;
        __syncthreads();
    }
    int eqr = sums[tid] - cnt_eq;
    __syncthreads();

    bool self[8];
    int cnt_sel = 0;
#pragma unroll
    for (int i = 0; i < 8; i++) {
        bool s = gtf[i] || (eqf[i] && (eqr < tie_take));
        if (eqf[i]) eqr++;
        self[i] = s;
        cnt_sel += s ? 1 : 0;
    }
    sums[tid] = cnt_sel; __syncthreads();
    for (int off = 1; off < 256; off <<= 1) {
        int x = (tid >= off) ? sums[tid - off] : 0;
        __syncthreads();
        sums[tid] += x;
        __syncthreads();
    }
    int pos = sums[tid] - cnt_sel;
#pragma unroll
    for (int i = 0; i < 8; i++)
        if (self[i]) g_sel[bh * SEL_STRIDE + pos++] = base + i;
}

// ---------------------------------------------------------------------------
// Phase 3: flash-style sparse attention for the selected queries, scatter out.
// Block: 256 thr, 64 gathered queries x full S loop in 64-key tiles.
// Smem exactly 48KB: Qs + (K|P shared buffer) + Vs.
// ---------------------------------------------------------------------------
__global__ __launch_bounds__(256, 2)
void attn_kernel(const float* __restrict__ q, const float* __restrict__ k,
                 const float* __restrict__ v, float* __restrict__ out, int u)
{
    __shared__ float Qs[64 * 64];
    __shared__ float KP[64 * 64];   // K (xor-swizzled), then P (plain)
    __shared__ float Vs[64 * 64];

    const int tid = threadIdx.x;
    const int tx = tid & 15, ty = tid >> 4;
    const int bh = blockIdx.y;
    const int q0 = blockIdx.x * 64;

    const int*   selp  = g_sel + bh * SEL_STRIDE;
    const float* kbase = k + (size_t)bh * S_ * D_;
    const float* vbase = v + (size_t)bh * S_ * D_;

    for (int lin = tid; lin < 4096; lin += 256) {
        int r = lin >> 6, d = lin & 63;
        int qi = q0 + r;
        float val = 0.f;
        if (qi < u) val = q[((size_t)bh * T_ + selp[qi]) * D_ + d];
        Qs[lin] = val;
    }

    float row_m[4], row_Z[4], O[4][4];
#pragma unroll
    for (int i = 0; i < 4; i++) {
        row_m[i] = -1e30f; row_Z[i] = 0.f;
#pragma unroll
        for (int j = 0; j < 4; j++) O[i][j] = 0.f;
    }

    for (int kt = 0; kt < S_ / 64; kt++) {
        __syncthreads();
        const float* kp = kbase + (size_t)kt * 64 * D_;
        const float* vp = vbase + (size_t)kt * 64 * D_;
        for (int lin = tid; lin < 4096; lin += 256) {
            int r = lin >> 6, d = lin & 63;
            KP[(r << 6) + (d ^ (r & 31))] = kp[lin];
            Vs[lin] = vp[lin];
        }
        __syncthreads();

        float acc[4][4];
#pragma unroll
        for (int i = 0; i < 4; i++)
#pragma unroll
            for (int j = 0; j < 4; j++) acc[i][j] = 0.f;

#pragma unroll 8
        for (int d = 0; d < 64; d++) {
            float qv[4], kv[4];
#pragma unroll
            for (int i = 0; i < 4; i++) qv[i] = Qs[((4 * ty + i) << 6) + d];
#pragma unroll
            for (int j = 0; j < 4; j++) {
                int c = tx + 16 * j;
                kv[j] = KP[(c << 6) + (d ^ (c & 31))];
            }
#pragma unroll
            for (int i = 0; i < 4; i++)
#pragma unroll
                for (int j = 0; j < 4; j++)
                    acc[i][j] = fmaf(qv[i], kv[j], acc[i][j]);
        }

        float p[4][4];
#pragma unroll
        for (int i = 0; i < 4; i++) {
            float tmax = -1e30f;
#pragma unroll
            for (int j = 0; j < 4; j++) {
                float s = fminf(fmaxf(acc[i][j] * SCALE, -50.f), 50.f);
                acc[i][j] = s;
                tmax = fmaxf(tmax, s);
            }
#pragma unroll
            for (int o = 8; o >= 1; o >>= 1)
                tmax = fmaxf(tmax, __shfl_xor_sync(0xffffffffu, tmax, o));

            float newm = fmaxf(row_m[i], tmax);
            float f = __expf(row_m[i] - newm);
            float zt = 0.f;
#pragma unroll
            for (int j = 0; j < 4; j++) {
                float e = __expf(acc[i][j] - newm);
                p[i][j] = e;
                zt += e;
            }
#pragma unroll
            for (int o = 8; o >= 1; o >>= 1)
                zt += __shfl_xor_sync(0xffffffffu, zt, o);

            row_Z[i] = row_Z[i] * f + zt;
#pragma unroll
            for (int j = 0; j < 4; j++) O[i][j] *= f;
            row_m[i] = newm;
        }
        __syncthreads();   // done reading KP as K

#pragma unroll
        for (int i = 0; i < 4; i++)
#pragma unroll
            for (int j = 0; j < 4; j++)
                KP[((4 * ty + i) << 6) + tx + 16 * j] = p[i][j];
        __syncthreads();

#pragma unroll 8
        for (int kk = 0; kk < 64; kk++) {
            float pv[4], vv[4];
#pragma unroll
            for (int i = 0; i < 4; i++) pv[i] = KP[((4 * ty + i) << 6) + kk];
#pragma unroll
            for (int j = 0; j < 4; j++) vv[j] = Vs[(kk << 6) + tx + 16 * j];
#pragma unroll
            for (int i = 0; i < 4; i++)
#pragma unroll
                for (int j = 0; j < 4; j++)
                    O[i][j] = fmaf(pv[i], vv[j], O[i][j]);
        }
    }

#pragma unroll
    for (int i = 0; i < 4; i++) {
        int qi = q0 + 4 * ty + i;
        if (qi < u) {
            int t = selp[qi];
            float inv = 1.0f / row_Z[i];
            float* op = out + ((size_t)bh * T_ + t) * D_;
#pragma unroll
            for (int j = 0; j < 4; j++)
                op[tx + 16 * j] = O[i][j] * inv;
        }
    }
}

// ---------------------------------------------------------------------------
extern "C" void kernel_launch(void* const* d_in, const int* in_sizes, int n_in,
                              void* d_out, int out_size)
{
    (void)in_sizes; (void)n_in;
    const float* q = (const float*)d_in[0];
    const float* k = (const float*)d_in[1];
    const float* v = (const float*)d_in[2];
    float* out = (float*)d_out;

    cudaMemsetAsync(d_out, 0, (size_t)out_size * sizeof(float), 0);

    dim3 g1(T_ / 64, BH);
    kl_kernel<<<g1, 256>>>(q, k);

    topk_kernel<<<BH, 256>>>(U_SEL);

    dim3 g3((U_SEL + 63) / 64, BH);
    attn_kernel<<<g3, 256>>>(q, k, v, out, U_SEL);
}

// round 3
// speedup vs baseline: 1.1847x; 1.1847x over previous
#include <cuda_runtime.h>
#include <math.h>

#define B_    2
#define H_    16
#define BH    32
#define T_    2048
#define S_    2048
#define D_    64
#define U_SEL 614        // max(int(min(0.4*ln(2048),1024)), int(0.3*2048)) = max(3,614)
#define SEL_STRIDE 640
#define SCALE 0.125f     // 1/sqrt(64)
#define LOGS  7.624618986159398  // log(2048)

__device__ float g_kl[BH * T_];
__device__ int   g_sel[BH * SEL_STRIDE];

// ---------------------------------------------------------------------------
// Phase 1: KL score per query. 64q x 128k tiles, thread tile 4x8.
// All smem traffic is float4 (LDS.128). K swizzled at 16B granularity:
// Ks4[c*16 + (dv ^ (c & 15))]. Accumulation order over d is strictly
// ascending (x,y,z,w) -> scores bitwise identical to the R2 kernel,
// so top-k selection is unchanged.
// ---------------------------------------------------------------------------
__global__ __launch_bounds__(256, 2)
void kl_kernel(const float* __restrict__ q, const float* __restrict__ k)
{
    __shared__ float4 Qs4[64 * 16];     // [row][dv] plain
    __shared__ float4 Ks4[128 * 16];    // [col][dv ^ (col&15)]

    const int tid = threadIdx.x;
    const int tx = tid & 15, ty = tid >> 4;
    const int bh = blockIdx.y;
    const int q0 = blockIdx.x * 64;

    const float4* qp4 = (const float4*)(q + ((size_t)bh * T_ + q0) * D_);
    const float4* kp4 = (const float4*)(k + (size_t)bh * S_ * D_);

    for (int lin = tid; lin < 64 * 16; lin += 256)
        Qs4[lin] = qp4[lin];

    float  row_m[4];
    double row_Z[4], row_A[4];
#pragma unroll
    for (int i = 0; i < 4; i++) { row_m[i] = -1e30f; row_Z[i] = 0.0; row_A[i] = 0.0; }

    for (int kt = 0; kt < S_ / 128; kt++) {
        __syncthreads();
        const float4* ktp4 = kp4 + (size_t)kt * 128 * 16;
        for (int lin = tid; lin < 128 * 16; lin += 256) {
            int r = lin >> 4, dv = lin & 15;
            Ks4[(r << 4) + (dv ^ (r & 15))] = ktp4[lin];
        }
        __syncthreads();

        float acc[4][8];
#pragma unroll
        for (int i = 0; i < 4; i++)
#pragma unroll
            for (int j = 0; j < 8; j++) acc[i][j] = 0.f;

#pragma unroll 4
        for (int dv = 0; dv < 16; dv++) {
            float4 qv[4], kv[8];
#pragma unroll
            for (int i = 0; i < 4; i++) qv[i] = Qs4[((4 * ty + i) << 4) + dv];
#pragma unroll
            for (int j = 0; j < 8; j++) {
                int c = tx + 16 * j;
                kv[j] = Ks4[(c << 4) + (dv ^ (c & 15))];
            }
#pragma unroll
            for (int i = 0; i < 4; i++)
#pragma unroll
                for (int j = 0; j < 8; j++) {
                    acc[i][j] = fmaf(qv[i].x, kv[j].x, acc[i][j]);
                    acc[i][j] = fmaf(qv[i].y, kv[j].y, acc[i][j]);
                    acc[i][j] = fmaf(qv[i].z, kv[j].z, acc[i][j]);
                    acc[i][j] = fmaf(qv[i].w, kv[j].w, acc[i][j]);
                }
        }

#pragma unroll
        for (int i = 0; i < 4; i++) {
            float tmax = -1e30f;
#pragma unroll
            for (int j = 0; j < 8; j++) {
                float s = fminf(fmaxf(acc[i][j] * SCALE, -50.f), 50.f);
                acc[i][j] = s;
                tmax = fmaxf(tmax, s);
            }
#pragma unroll
            for (int o = 8; o >= 1; o >>= 1)
                tmax = fmaxf(tmax, __shfl_xor_sync(0xffffffffu, tmax, o));

            float newm = fmaxf(row_m[i], tmax);
            float zt = 0.f, at = 0.f;
#pragma unroll
            for (int j = 0; j < 8; j++) {
                float p = acc[i][j] - newm;
                float e = __expf(p);
                zt += e;
                at = fmaf(e, p, at);
            }
#pragma unroll
            for (int o = 8; o >= 1; o >>= 1) {
                zt += __shfl_xor_sync(0xffffffffu, zt, o);
                at += __shfl_xor_sync(0xffffffffu, at, o);
            }
            float dm = row_m[i] - newm;
            float f  = __expf(dm);
            row_A[i] = (double)f * (row_A[i] + (double)dm * row_Z[i]) + (double)at;
            row_Z[i] = (double)f * row_Z[i] + (double)zt;
            row_m[i] = newm;
        }
    }

    if (tx == 0) {
#pragma unroll
        for (int i = 0; i < 4; i++) {
            double kl = row_A[i] / row_Z[i] - log(row_Z[i]) + LOGS;
            g_kl[bh * T_ + q0 + 4 * ty + i] = (float)kl;
        }
    }
}

// ---------------------------------------------------------------------------
// Phase 2: exact top-u via 8-bit MSB radix select, stable low-index tie-break.
// ---------------------------------------------------------------------------
__global__ void topk_kernel(int u)
{
    const int bh = blockIdx.x;
    const int tid = threadIdx.x;   // 256
    __shared__ unsigned keys[T_];
    __shared__ int hist[256];
    __shared__ int sums[256];
    __shared__ int sh_digit, sh_need;

    for (int t = tid; t < T_; t += 256) {
        unsigned b = __float_as_uint(g_kl[bh * T_ + t]);
        keys[t] = (b & 0x80000000u) ? ~b : (b | 0x80000000u);
    }
    __syncthreads();

    unsigned prefix = 0u, pmask = 0u;
    int need = u;
    for (int shift = 24; shift >= 0; shift -= 8) {
        hist[tid] = 0;
        __syncthreads();
        for (int t = tid; t < T_; t += 256) {
            unsigned kk = keys[t];
            if ((kk & pmask) == prefix)
                atomicAdd(&hist[(kk >> shift) & 255u], 1);
        }
        __syncthreads();
        if (tid == 0) {
            int cum = 0, d = 255;
            for (; d > 0; d--) {
                if (cum + hist[d] >= need) break;
                cum += hist[d];
            }
            sh_digit = d;
            sh_need  = need - cum;
        }
        __syncthreads();
        prefix |= ((unsigned)sh_digit) << shift;
        pmask  |= (255u << shift);
        need = sh_need;
        __syncthreads();
    }
    const unsigned thr = prefix;
    const int tie_take = need;

    const int base = tid * (T_ / 256);
    bool gtf[8], eqf[8];
    int cnt_eq = 0;
#pragma unroll
    for (int i = 0; i < 8; i++) {
        unsigned kk = keys[base + i];
        gtf[i] = (kk > thr);
        eqf[i] = (kk == thr);
        cnt_eq += eqf[i] ? 1 : 0;
    }
    sums[tid] = cnt_eq; __syncthreads();
    for (int off = 1; off < 256; off <<= 1) {
        int x = (tid >= off) ? sums[tid - off] : 0;
        __syncthreads();
        sums[tid] += x;
        __syncthreads();
    }
    int eqr = sums[tid] - cnt_eq;
    __syncthreads();

    bool self[8];
    int cnt_sel = 0;
#pragma unroll
    for (int i = 0; i < 8; i++) {
        bool s = gtf[i] || (eqf[i] && (eqr < tie_take));
        if (eqf[i]) eqr++;
        self[i] = s;
        cnt_sel += s ? 1 : 0;
    }
    sums[tid] = cnt_sel; __syncthreads();
    for (int off = 1; off < 256; off <<= 1) {
        int x = (tid >= off) ? sums[tid - off] : 0;
        __syncthreads();
        sums[tid] += x;
        __syncthreads();
    }
    int pos = sums[tid] - cnt_sel;
#pragma unroll
    for (int i = 0; i < 8; i++)
        if (self[i]) g_sel[bh * SEL_STRIDE + pos++] = base + i;
}

// ---------------------------------------------------------------------------
// Phase 3: sparse attention. 64q x 64k tiles, thread tile 4q x 4 contiguous
// output cols (float4 accumulators). 3 CTAs/SM -> 320 blocks in one wave.
// ---------------------------------------------------------------------------
__global__ __launch_bounds__(256, 3)
void attn_kernel(const float* __restrict__ q, const float* __restrict__ k,
                 const float* __restrict__ v, float* __restrict__ out, int u)
{
    __shared__ float4 Qs4[64 * 16];
    __shared__ float4 KP4[64 * 16];   // K (swizzled), then P (plain)
    __shared__ float4 Vs4[64 * 16];

    const int tid = threadIdx.x;
    const int tx = tid & 15, ty = tid >> 4;
    const int bh = blockIdx.y;
    const int q0 = blockIdx.x * 64;

    const int*    selp = g_sel + bh * SEL_STRIDE;
    const float4* kb4  = (const float4*)(k + (size_t)bh * S_ * D_);
    const float4* vb4  = (const float4*)(v + (size_t)bh * S_ * D_);
    const float4* qg4  = (const float4*)q;

    for (int lin = tid; lin < 64 * 16; lin += 256) {
        int r = lin >> 4, dv = lin & 15;
        int qi = q0 + r;
        float4 val = make_float4(0.f, 0.f, 0.f, 0.f);
        if (qi < u) val = qg4[((size_t)bh * T_ + selp[qi]) * 16 + dv];
        Qs4[lin] = val;
    }

    float row_m[4], row_Z[4];
    float4 O4[4];
#pragma unroll
    for (int i = 0; i < 4; i++) {
        row_m[i] = -1e30f; row_Z[i] = 0.f;
        O4[i] = make_float4(0.f, 0.f, 0.f, 0.f);
    }

    for (int kt = 0; kt < S_ / 64; kt++) {
        __syncthreads();
        const float4* kp4 = kb4 + (size_t)kt * 64 * 16;
        const float4* vp4 = vb4 + (size_t)kt * 64 * 16;
        for (int lin = tid; lin < 64 * 16; lin += 256) {
            int r = lin >> 4, dv = lin & 15;
            KP4[(r << 4) + (dv ^ (r & 15))] = kp4[lin];
            Vs4[lin] = vp4[lin];
        }
        __syncthreads();

        float acc[4][4];
#pragma unroll
        for (int i = 0; i < 4; i++)
#pragma unroll
            for (int j = 0; j < 4; j++) acc[i][j] = 0.f;

#pragma unroll 4
        for (int dv = 0; dv < 16; dv++) {
            float4 qv[4], kv[4];
#pragma unroll
            for (int i = 0; i < 4; i++) qv[i] = Qs4[((4 * ty + i) << 4) + dv];
#pragma unroll
            for (int j = 0; j < 4; j++) {
                int c = tx + 16 * j;
                kv[j] = KP4[(c << 4) + (dv ^ (c & 15))];
            }
#pragma unroll
            for (int i = 0; i < 4; i++)
#pragma unroll
                for (int j = 0; j < 4; j++) {
                    acc[i][j] = fmaf(qv[i].x, kv[j].x, acc[i][j]);
                    acc[i][j] = fmaf(qv[i].y, kv[j].y, acc[i][j]);
                    acc[i][j] = fmaf(qv[i].z, kv[j].z, acc[i][j]);
                    acc[i][j] = fmaf(qv[i].w, kv[j].w, acc[i][j]);
                }
        }

        float p[4][4];
#pragma unroll
        for (int i = 0; i < 4; i++) {
            float tmax = -1e30f;
#pragma unroll
            for (int j = 0; j < 4; j++) {
                float s = fminf(fmaxf(acc[i][j] * SCALE, -50.f), 50.f);
                acc[i][j] = s;
                tmax = fmaxf(tmax, s);
            }
#pragma unroll
            for (int o = 8; o >= 1; o >>= 1)
                tmax = fmaxf(tmax, __shfl_xor_sync(0xffffffffu, tmax, o));

            float newm = fmaxf(row_m[i], tmax);
            float f = __expf(row_m[i] - newm);
            float zt = 0.f;
#pragma unroll
            for (int j = 0; j < 4; j++) {
                float e = __expf(acc[i][j] - newm);
                p[i][j] = e;
                zt += e;
            }
#pragma unroll
            for (int o = 8; o >= 1; o >>= 1)
                zt += __shfl_xor_sync(0xffffffffu, zt, o);

            row_Z[i] = row_Z[i] * f + zt;
            O4[i].x *= f; O4[i].y *= f; O4[i].z *= f; O4[i].w *= f;
            row_m[i] = newm;
        }
        __syncthreads();   // done reading KP4 as K

        float* Pf = (float*)KP4;
#pragma unroll
        for (int i = 0; i < 4; i++)
#pragma unroll
            for (int j = 0; j < 4; j++)
                Pf[((4 * ty + i) << 6) + tx + 16 * j] = p[i][j];
        __syncthreads();

#pragma unroll 4
        for (int kkv = 0; kkv < 16; kkv++) {
            float4 pv[4], vv[4];
#pragma unroll
            for (int i = 0; i < 4; i++) pv[i] = KP4[((4 * ty + i) << 4) + kkv];
#pragma unroll
            for (int m = 0; m < 4; m++) vv[m] = Vs4[((4 * kkv + m) << 4) + tx];
#pragma unroll
            for (int i = 0; i < 4; i++) {
                O4[i].x = fmaf(pv[i].x, vv[0].x, O4[i].x);
                O4[i].y = fmaf(pv[i].x, vv[0].y, O4[i].y);
                O4[i].z = fmaf(pv[i].x, vv[0].z, O4[i].z);
                O4[i].w = fmaf(pv[i].x, vv[0].w, O4[i].w);
                O4[i].x = fmaf(pv[i].y, vv[1].x, O4[i].x);
                O4[i].y = fmaf(pv[i].y, vv[1].y, O4[i].y);
                O4[i].z = fmaf(pv[i].y, vv[1].z, O4[i].z);
                O4[i].w = fmaf(pv[i].y, vv[1].w, O4[i].w);
                O4[i].x = fmaf(pv[i].z, vv[2].x, O4[i].x);
                O4[i].y = fmaf(pv[i].z, vv[2].y, O4[i].y);
                O4[i].z = fmaf(pv[i].z, vv[2].z, O4[i].z);
                O4[i].w = fmaf(pv[i].z, vv[2].w, O4[i].w);
                O4[i].x = fmaf(pv[i].w, vv[3].x, O4[i].x);
                O4[i].y = fmaf(pv[i].w, vv[3].y, O4[i].y);
                O4[i].z = fmaf(pv[i].w, vv[3].z, O4[i].z);
                O4[i].w = fmaf(pv[i].w, vv[3].w, O4[i].w);
            }
        }
    }

#pragma unroll
    for (int i = 0; i < 4; i++) {
        int qi = q0 + 4 * ty + i;
        if (qi < u) {
            int t = selp[qi];
            float inv = 1.0f / row_Z[i];
            float4 o = make_float4(O4[i].x * inv, O4[i].y * inv,
                                   O4[i].z * inv, O4[i].w * inv);
            float4* op4 = (float4*)(out + ((size_t)bh * T_ + t) * D_);
            op4[tx] = o;
        }
    }
}

// ---------------------------------------------------------------------------
extern "C" void kernel_launch(void* const* d_in, const int* in_sizes, int n_in,
                              void* d_out, int out_size)
{
    (void)in_sizes; (void)n_in;
    const float* q = (const float*)d_in[0];
    const float* k = (const float*)d_in[1];
    const float* v = (const float*)d_in[2];
    float* out = (float*)d_out;

    cudaMemsetAsync(d_out, 0, (size_t)out_size * sizeof(float), 0);

    dim3 g1(T_ / 64, BH);
    kl_kernel<<<g1, 256>>>(q, k);

    topk_kernel<<<BH, 256>>>(U_SEL);

    dim3 g3((U_SEL + 63) / 64, BH);
    attn_kernel<<<g3, 256>>>(q, k, v, out, U_SEL);
}